// round 6
// baseline (speedup 1.0000x reference)
#include <cuda_runtime.h>

#define Dn 32
#define Ln 65536

// ---- f32x2 packed helpers (Blackwell sm_100+) ----
__device__ __forceinline__ unsigned long long pack2(float lo, float hi) {
    unsigned long long r;
    asm("mov.b64 %0, {%1, %2};" : "=l"(r) : "f"(lo), "f"(hi));
    return r;
}
__device__ __forceinline__ unsigned long long fma2(unsigned long long a,
                                                   unsigned long long b,
                                                   unsigned long long c) {
    unsigned long long d;
    asm("fma.rn.f32x2 %0, %1, %2, %3;" : "=l"(d) : "l"(a), "l"(b), "l"(c));
    return d;
}
__device__ __forceinline__ float2 unpack2(unsigned long long v) {
    float2 f;
    asm("mov.b64 {%0, %1}, %2;" : "=f"(f.x), "=f"(f.y) : "l"(v));
    return f;
}

// One thread: 8 consecutive output positions, all 4 output channels of one
// (batch, relation). Accumulators are f32x2 packed over (o0,o1)/(o2,o3).
// Weights are packed in-block into shared (single graph node — no staging
// kernels/memcpys). __launch_bounds__(256,4) caps regs at 64 so ptxas
// rematerializes the warp-uniform LDS.128 weight reads instead of keeping
// all pairs live (Round 4's regs=78 trap) -> 4 CTAs/SM.
__global__ __launch_bounds__(256, 4)
void conv4x8x5_kernel(const float* __restrict__ x,
                      const float* __restrict__ k0, const float* __restrict__ k1,
                      const float* __restrict__ k2, const float* __restrict__ k3,
                      float* __restrict__ y)
{
    __shared__ ulonglong2 shW[40];   // [i*5+w] = ( pack(k0o,k1o), pack(k2o,k3o) )

    const int r = blockIdx.y;
    const int b = blockIdx.z;
    const int t = threadIdx.x;

    if (t < 40) {
        const float* ker = (r == 0) ? k0 : (r == 1) ? k1 : (r == 2) ? k2 : k3;
        const int i = t / 5;
        const int w = t % 5;
        ulonglong2 v;
        v.x = pack2(ker[0 * 40 + i * 5 + w], ker[1 * 40 + i * 5 + w]);
        v.y = pack2(ker[2 * 40 + i * 5 + w], ker[3 * 40 + i * 5 + w]);
        shW[t] = v;
    }
    __syncthreads();

    const int l0 = (blockIdx.x * 256 + t) * 8;

    unsigned long long acc[2][8];
    #pragma unroll
    for (int op = 0; op < 2; op++)
        #pragma unroll
        for (int p = 0; p < 8; p++)
            acc[op][p] = 0ull;

    const float* xb = x + ((size_t)(b * Dn + 8 * r) * Ln) + l0;

    #pragma unroll 2
    for (int i = 0; i < 8; i++) {
        const float* xc = xb + (size_t)i * Ln;

        // positions l0-2 .. l0+9 (halo = one aligned float2 each side)
        float2 lo = (l0 > 0)      ? *(const float2*)(xc - 2) : make_float2(0.f, 0.f);
        float4 m0 = *(const float4*)(xc);
        float4 m1 = *(const float4*)(xc + 4);
        float2 hi = (l0 < Ln - 8) ? *(const float2*)(xc + 8) : make_float2(0.f, 0.f);

        float xv[12];
        xv[0]  = lo.x; xv[1]  = lo.y;
        xv[2]  = m0.x; xv[3]  = m0.y; xv[4]  = m0.z; xv[5]  = m0.w;
        xv[6]  = m1.x; xv[7]  = m1.y; xv[8]  = m1.z; xv[9]  = m1.w;
        xv[10] = hi.x; xv[11] = hi.y;

        unsigned long long dup[12];
        #pragma unroll
        for (int j = 0; j < 12; j++) dup[j] = pack2(xv[j], xv[j]);

        #pragma unroll
        for (int w = 0; w < 5; w++) {
            const ulonglong2 wv = shW[i * 5 + w];   // warp-uniform LDS.128 broadcast
            #pragma unroll
            for (int p = 0; p < 8; p++) {
                acc[0][p] = fma2(wv.x, dup[p + w], acc[0][p]);
                acc[1][p] = fma2(wv.y, dup[p + w], acc[1][p]);
            }
        }
    }

    // Unpack o-pairs and store 4 contiguous rows (channels 4r..4r+3)
    float res[4][8];
    #pragma unroll
    for (int op = 0; op < 2; op++)
        #pragma unroll
        for (int p = 0; p < 8; p++) {
            const float2 f = unpack2(acc[op][p]);
            res[2 * op][p]     = f.x;
            res[2 * op + 1][p] = f.y;
        }

    float* yb = y + ((size_t)(b * 16 + 4 * r) * Ln) + l0;
    #pragma unroll
    for (int o = 0; o < 4; o++) {
        float* row = yb + (size_t)o * Ln;
        *(float4*)(row)     = make_float4(res[o][0], res[o][1], res[o][2], res[o][3]);
        *(float4*)(row + 4) = make_float4(res[o][4], res[o][5], res[o][6], res[o][7]);
    }
}

extern "C" void kernel_launch(void* const* d_in, const int* in_sizes, int n_in,
                              void* d_out, int out_size)
{
    const float* x  = (const float*)d_in[0];
    const float* k0 = (const float*)d_in[1];
    const float* k1 = (const float*)d_in[2];
    const float* k2 = (const float*)d_in[3];
    const float* k3 = (const float*)d_in[4];
    float* y = (float*)d_out;

    // Single graph node: weight packing folded into each block.
    // 8 positions/thread, 256 threads/block -> 2048 positions/block.
    dim3 grid(Ln / 2048, 4, 32);  // (pos tiles, relation, batch)
    dim3 block(256);
    conv4x8x5_kernel<<<grid, block>>>(x, k0, k1, k2, k3, y);
}

// round 7
// speedup vs baseline: 1.1530x; 1.1530x over previous
#include <cuda_runtime.h>

#define Dn 32
#define Ln 65536

// Dup'd weights in constant bank: cWd[((r*8+i)*5+w)*4+o] = pack(k, k)
__constant__ unsigned long long cWd[640];

// Staging buffer written by the pack kernel, then memcpy'd into cWd.
__device__ unsigned long long gPackD[640];

// ---- f32x2 packed helpers (Blackwell sm_100+) ----
__device__ __forceinline__ unsigned long long pack2(float lo, float hi) {
    unsigned long long r;
    asm("mov.b64 %0, {%1, %2};" : "=l"(r) : "f"(lo), "f"(hi));
    return r;
}
__device__ __forceinline__ unsigned long long fma2(unsigned long long a,
                                                   unsigned long long b,
                                                   unsigned long long c) {
    unsigned long long d;
    asm("fma.rn.f32x2 %0, %1, %2, %3;" : "=l"(d) : "l"(a), "l"(b), "l"(c));
    return d;
}

// Stage 1: dup-pack the 4 (4,8,5) kernels: one (k,k) u64 per (r,i,w,o).
__global__ void pack_weights_kernel(const float* __restrict__ k0,
                                    const float* __restrict__ k1,
                                    const float* __restrict__ k2,
                                    const float* __restrict__ k3)
{
    const int t = threadIdx.x;            // 0..639
    if (t >= 640) return;
    const int o = t & 3;
    const int w = (t >> 2) % 5;
    const int i = (t >> 2) / 5 % 8;
    const int r = t / 160;
    const float* ker = (r == 0) ? k0 : (r == 1) ? k1 : (r == 2) ? k2 : k3;
    const float v = ker[o * 40 + i * 5 + w];
    gPackD[t] = pack2(v, v);
}

// One thread: 8 consecutive output positions, all 4 output channels of one
// (batch, relation). Accumulators are f32x2 packed over POSITION pairs
// (out[2q], out[2q+1]) so:
//  - weight operand is a dup'd (k,k) u64 straight from the constant bank
//    (uniform path, zero packs, zero regular-RF cost),
//  - epilogue stores acc pairs directly as STG.128 (no unpacking).
__global__ __launch_bounds__(256, 4)
void conv4x8x5_kernel(const float* __restrict__ x, float* __restrict__ y)
{
    const int r = blockIdx.y;
    const int b = blockIdx.z;
    const unsigned long long* kr = cWd + r * 160;  // [(i*5+w)*4 + o]

    const int t  = threadIdx.x;
    const int l0 = (blockIdx.x * 256 + t) * 8;

    unsigned long long acc[4][4];   // [o][q] : q-th position pair
    #pragma unroll
    for (int o = 0; o < 4; o++)
        #pragma unroll
        for (int q = 0; q < 4; q++)
            acc[o][q] = 0ull;

    const float* xb = x + ((size_t)(b * Dn + 8 * r) * Ln) + l0;

    #pragma unroll 2
    for (int i = 0; i < 8; i++) {
        const float* xc = xb + (size_t)i * Ln;

        // positions l0-2 .. l0+9 (halo = one aligned float2 each side)
        float2 lo = (l0 > 0)      ? *(const float2*)(xc - 2) : make_float2(0.f, 0.f);
        float4 m0 = *(const float4*)(xc);
        float4 m1 = *(const float4*)(xc + 4);
        float2 hi = (l0 < Ln - 8) ? *(const float2*)(xc + 8) : make_float2(0.f, 0.f);

        float xv[12];
        xv[0]  = lo.x; xv[1]  = lo.y;
        xv[2]  = m0.x; xv[3]  = m0.y; xv[4]  = m0.z; xv[5]  = m0.w;
        xv[6]  = m1.x; xv[7]  = m1.y; xv[8]  = m1.z; xv[9]  = m1.w;
        xv[10] = hi.x; xv[11] = hi.y;

        // consecutive-position pairs: xp[j] = (x[l0+j-2], x[l0+j-1])
        unsigned long long xp[11];
        #pragma unroll
        for (int j = 0; j < 11; j++) xp[j] = pack2(xv[j], xv[j + 1]);

        #pragma unroll
        for (int w = 0; w < 5; w++) {
            const unsigned long long* wd = kr + (i * 5 + w) * 4;
            const unsigned long long w0 = wd[0];   // uniform const loads,
            const unsigned long long w1 = wd[1];   // already (k,k)-dup'd
            const unsigned long long w2 = wd[2];
            const unsigned long long w3 = wd[3];
            #pragma unroll
            for (int q = 0; q < 4; q++) {
                const unsigned long long xq = xp[2 * q + w];
                acc[0][q] = fma2(w0, xq, acc[0][q]);
                acc[1][q] = fma2(w1, xq, acc[1][q]);
                acc[2][q] = fma2(w2, xq, acc[2][q]);
                acc[3][q] = fma2(w3, xq, acc[3][q]);
            }
        }
    }

    // acc[o][q] already holds (out[2q], out[2q+1]) — store directly.
    float* yb = y + ((size_t)(b * 16 + 4 * r) * Ln) + l0;
    #pragma unroll
    for (int o = 0; o < 4; o++) {
        float* row = yb + (size_t)o * Ln;
        ulonglong2 s0; s0.x = acc[o][0]; s0.y = acc[o][1];
        ulonglong2 s1; s1.x = acc[o][2]; s1.y = acc[o][3];
        *(ulonglong2*)(row)     = s0;
        *(ulonglong2*)(row + 4) = s1;
    }
}

extern "C" void kernel_launch(void* const* d_in, const int* in_sizes, int n_in,
                              void* d_out, int out_size)
{
    const float* x  = (const float*)d_in[0];
    const float* k0 = (const float*)d_in[1];
    const float* k1 = (const float*)d_in[2];
    const float* k2 = (const float*)d_in[3];
    const float* k3 = (const float*)d_in[4];
    float* y = (float*)d_out;

    // Stage 1: dup-pack weights (1 node).
    pack_weights_kernel<<<1, 640>>>(k0, k1, k2, k3);

    // Stage 2: single D2D memcpy into the constant bank (1 node).
    void* src = nullptr;
    cudaGetSymbolAddress(&src, gPackD);
    cudaMemcpyToSymbolAsync(cWd, src, 640 * sizeof(unsigned long long), 0,
                            cudaMemcpyDeviceToDevice, 0);

    // Stage 3: the conv. 8 positions/thread, 256 threads/block.
    dim3 grid(Ln / 2048, 4, 32);  // (pos tiles, relation, batch)
    dim3 block(256);
    conv4x8x5_kernel<<<grid, block>>>(x, y);
}